// round 10
// baseline (speedup 1.0000x reference)
#include <cuda_runtime.h>
#include <cstdint>

#define M_ROWS 65536
#define N_COLS 640
#define K_DIM  512
#define GROUPS 2
#define NUM_VARS 320
#define CB_DIM 128
#define EPSV 1e-7f
#define NEG_HUGE -3.402823466e38f
#define GAP_THR 0.25f

// ---------------------------------------------------------------------------
// Static device scratch (no cudaMalloc allowed)
// ---------------------------------------------------------------------------
__device__ float        g_logits[(size_t)M_ROWS * N_COLS];
__device__ uint32_t     g_xh[(size_t)M_ROWS * (K_DIM / 2)];     // x fp16x2, k-pair packed
__device__ float        g_wt[(size_t)N_COLS * K_DIM];           // W^T fp32 (exact recheck)
__device__ uint32_t     g_wth[(size_t)N_COLS * (K_DIM / 2)];    // W^T fp16x2, k-pair packed
__device__ float        g_probsum[N_COLS];
__device__ unsigned int g_counts[N_COLS];
__device__ unsigned int g_done;                                 // last-block ticket

// ---------------------------------------------------------------------------
// Helpers (baseline sm_103 PTX only: cp.async, mma.sync fp16, redux.sync)
// ---------------------------------------------------------------------------
__device__ __forceinline__ uint32_t smem_to_u32(const void* p) {
    uint32_t a;
    asm("{ .reg .u64 t; cvta.to.shared.u64 t, %1; cvt.u32.u64 %0, t; }" : "=r"(a) : "l"(p));
    return a;
}
__device__ __forceinline__ void cp16(uint32_t s, const void* g) {
    asm volatile("cp.async.cg.shared.global [%0], [%1], 16;" :: "r"(s), "l"(g) : "memory");
}
__device__ __forceinline__ void cp_commit() {
    asm volatile("cp.async.commit_group;" ::: "memory");
}
// pack two consecutive-k floats into fp16x2 (low half = even k)
__device__ __forceinline__ uint32_t h2pack(float e, float o) {
    uint32_t h;
    asm("cvt.rn.f16x2.f32 %0, %1, %2;" : "=r"(h) : "f"(o), "f"(e));
    return h;
}
__device__ __forceinline__ void mma_fp16(float* c, const uint32_t* a, const uint32_t* b) {
    asm volatile(
        "mma.sync.aligned.m16n8k16.row.col.f32.f16.f16.f32 "
        "{%0,%1,%2,%3}, {%4,%5,%6,%7}, {%8,%9}, {%0,%1,%2,%3};"
        : "+f"(c[0]), "+f"(c[1]), "+f"(c[2]), "+f"(c[3])
        : "r"(a[0]), "r"(a[1]), "r"(a[2]), "r"(a[3]), "r"(b[0]), "r"(b[1]));
}
// exact warp-max of a float via order-preserving u32 keys + redux.sync
__device__ __forceinline__ float warp_max_f32(float v) {
    uint32_t u = __float_as_uint(v);
    uint32_t key = ((int)u < 0) ? ~u : (u | 0x80000000u);
    uint32_t kmax;
    asm("redux.sync.max.u32 %0, %1, 0xffffffff;" : "=r"(kmax) : "r"(key));
    uint32_t ub = (kmax & 0x80000000u) ? (kmax & 0x7fffffffu) : ~kmax;
    return __uint_as_float(ub);
}

// ---------------------------------------------------------------------------
// Kernel 0: combined prep.  Blocks [0,80): W transpose (fp32 recheck copy) +
// fp16 pack.  Blocks [80,...): stream-pack x to fp16x2 (4 float4/thread).
// Block 0 also zeroes the cross-block accumulators (graph replay reset).
// ---------------------------------------------------------------------------
#define WPREP_BLOCKS 80                                      // 8 * 10
#define XPACK_TOT    (M_ROWS * (K_DIM / 4))                  // total float4s
#define XPACK_BLOCKS (XPACK_TOT / (256 * 4))                 // 8192

__global__ __launch_bounds__(256)
void prep_kernel(const float* __restrict__ W, const float* __restrict__ x) {
    const int tid = threadIdx.x;
    if (blockIdx.x >= WPREP_BLOCKS) {
        const size_t base = (size_t)(blockIdx.x - WPREP_BLOCKS) * 256 + tid;
#pragma unroll
        for (int q = 0; q < 4; q++) {
            const size_t i = base + (size_t)q * (XPACK_TOT / 4);
            const float4 v = ((const float4*)x)[i];
            uint2 o;
            o.x = h2pack(v.x, v.y);
            o.y = h2pack(v.z, v.w);
            ((uint2*)g_xh)[i] = o;
        }
        return;
    }

    __shared__ float t[64][65];
    const int kt = (blockIdx.x & 7) * 64, nt = (blockIdx.x >> 3) * 64;

    if (blockIdx.x == 0) {
        for (int i = tid; i < N_COLS; i += 256) { g_probsum[i] = 0.0f; g_counts[i] = 0u; }
    }

    for (int i = tid; i < 64 * 64; i += 256) {
        int k = i >> 6, n = i & 63;
        t[k][n] = W[(size_t)(kt + k) * N_COLS + nt + n];
    }
    __syncthreads();
    for (int i = tid; i < 64 * 64; i += 256) {
        int n = i >> 6, k = i & 63;
        g_wt[(size_t)(nt + n) * K_DIM + kt + k] = t[k][n];
    }
    for (int i = tid; i < 64 * 32; i += 256) {
        int n = i >> 5, w = i & 31;
        g_wth[(size_t)(nt + n) * (K_DIM / 2) + (kt >> 1) + w] =
            h2pack(t[2 * w][n], t[2 * w + 1][n]);
    }
}

// ---------------------------------------------------------------------------
// Kernel 1: single-pass fp16 GEMM, mma.sync.m16n8k16 (fp32 accumulate).
// CTA 128x128, 8 warps (warp tile 32x64).  K-chunks of 64 fp32 (=32 words),
// 3-stage cp.async pipeline, one barrier per chunk (8 total).  Smem rows
// padded to 36 words -> all fragment LDS conflict-free (4*grp+tg mod 32).
// ---------------------------------------------------------------------------
#define SM_STRIDE 36
#define TILE_B    (128 * SM_STRIDE * 4)   // 18432 bytes per tile
#define STAGE_B   (2 * TILE_B)            // 36864 (A + B)
#define GEMM_SMEM (3 * STAGE_B)           // 110592
#define NCHUNK 8

__global__ __launch_bounds__(256, 2)
void gemm_fp16_kernel(const float* __restrict__ bias)  // b [640]
{
    extern __shared__ char smem[];
    const int tid  = threadIdx.x;
    const int wid  = tid >> 5;
    const int lane = tid & 31;
    const int bm   = blockIdx.y * 128;
    const int bn   = blockIdx.x * 128;
    const int wm   = wid & 3;      // M-warp 0..3 -> rows wm*32..+32
    const int wn   = wid >> 2;     // N-warp 0..1 -> cols wn*64..+64
    const int grp  = lane >> 2;    // 0..7
    const int tg   = lane & 3;     // 0..3
    const uint32_t sb = smem_to_u32(smem);

    float acc[2][8][4];
#pragma unroll
    for (int mf = 0; mf < 2; mf++)
#pragma unroll
        for (int nf = 0; nf < 8; nf++)
#pragma unroll
            for (int r = 0; r < 4; r++) acc[mf][nf][r] = 0.0f;

    // loader mapping: thread -> (row 0..127, half 0/1 of the 32-word chunk row)
    const int lr = tid >> 1;
    const int lh = tid & 1;
    const uint32_t* Ag = g_xh  + (size_t)(bm + lr) * (K_DIM / 2) + lh * 16;
    const uint32_t* Bg = g_wth + (size_t)(bn + lr) * (K_DIM / 2) + lh * 16;
    const uint32_t  dst = (uint32_t)(lr * SM_STRIDE + lh * 16) * 4;

#define CP_CHUNK(c, stg) do {                                                    \
        uint32_t _s = sb + (uint32_t)(stg) * STAGE_B + dst;                      \
        const uint32_t* _ga = Ag + (c) * 32;                                     \
        cp16(_s,      _ga);      cp16(_s + 16, _ga + 4);                         \
        cp16(_s + 32, _ga + 8);  cp16(_s + 48, _ga + 12);                        \
        uint32_t _sB = _s + TILE_B;                                              \
        const uint32_t* _gb = Bg + (c) * 32;                                     \
        cp16(_sB,      _gb);     cp16(_sB + 16, _gb + 4);                        \
        cp16(_sB + 32, _gb + 8); cp16(_sB + 48, _gb + 12);                       \
        cp_commit();                                                             \
    } while (0)

    CP_CHUNK(0, 0);
    CP_CHUNK(1, 1);

    for (int c = 0; c < NCHUNK; c++) {
        const int st = c % 3;
        if (c < NCHUNK - 1) asm volatile("cp.async.wait_group 1;" ::: "memory");
        else                asm volatile("cp.async.wait_group 0;" ::: "memory");
        __syncthreads();

        if (c + 2 < NCHUNK) CP_CHUNK(c + 2, (c + 2) % 3);

        const uint32_t* Ah = (const uint32_t*)(smem + (size_t)st * STAGE_B);
        const uint32_t* Bh = (const uint32_t*)(smem + (size_t)st * STAGE_B + TILE_B);

#pragma unroll
        for (int ks = 0; ks < 4; ks++) {
            const int w0 = ks * 8 + tg;
            uint32_t af[2][4];
#pragma unroll
            for (int mf = 0; mf < 2; mf++) {
                const int r = wm * 32 + mf * 16 + grp;
                af[mf][0] = Ah[r * SM_STRIDE + w0];
                af[mf][1] = Ah[(r + 8) * SM_STRIDE + w0];
                af[mf][2] = Ah[r * SM_STRIDE + w0 + 4];
                af[mf][3] = Ah[(r + 8) * SM_STRIDE + w0 + 4];
            }
#pragma unroll
            for (int nf = 0; nf < 8; nf++) {
                const int nr = wn * 64 + nf * 8 + grp;
                uint32_t bf[2];
                bf[0] = Bh[nr * SM_STRIDE + w0];
                bf[1] = Bh[nr * SM_STRIDE + w0 + 4];
#pragma unroll
                for (int mf = 0; mf < 2; mf++)
                    mma_fp16(acc[mf][nf], af[mf], bf);
            }
        }
    }

    // epilogue: bias add, store logits
#pragma unroll
    for (int mf = 0; mf < 2; mf++) {
        const int row = bm + wm * 32 + mf * 16 + grp;
#pragma unroll
        for (int nf = 0; nf < 8; nf++) {
            const int col = bn + wn * 64 + nf * 8 + tg * 2;
            const float b0 = __ldg(&bias[col]);
            const float b1 = __ldg(&bias[col + 1]);
            float2 v0 = make_float2(acc[mf][nf][0] + b0, acc[mf][nf][1] + b1);
            float2 v1 = make_float2(acc[mf][nf][2] + b0, acc[mf][nf][3] + b1);
            *(float2*)&g_logits[(size_t)row * N_COLS + col]       = v0;
            *(float2*)&g_logits[(size_t)(row + 8) * N_COLS + col] = v1;
        }
    }
}

// ---------------------------------------------------------------------------
// Kernel 2: per-row argmax + softmax + codebook gather + (last block) final
// perplexities.
//  - logits tiles double-buffered via cp.async
//  - warp max via redux.sync; candidate-set exact fp32 recheck (unchanged)
//  - per-lane logits cached in registers (1 smem read instead of 3)
//  - gather via float4 (4 rows x 64 lanes)
//  - finalize folded in via last-block ticket
// ---------------------------------------------------------------------------
#define RPB   32
#define BATCH 8
#define NJ    (NUM_VARS / 32)    // 10

__global__ __launch_bounds__(256)
void reduce_kernel(const float* __restrict__ codebook,   // [640, 128]
                   const float* __restrict__ x,          // [65536, 512]
                   const float* __restrict__ bias,       // [640]
                   float* __restrict__ out,              // [65536, 256]
                   float* __restrict__ out2)             // 2 perplexity scalars
{
    __shared__ __align__(16) float sl[2][BATCH][N_COLS];   // 40960 B
    __shared__ float sinv[BATCH][2];
    __shared__ int   sk[BATCH][2];
    __shared__ unsigned int shist[N_COLS];
    __shared__ unsigned int sticket;

    const int tid  = threadIdx.x;
    const int lane = tid & 31;
    const int warp = tid >> 5;
    const uint32_t slb = smem_to_u32(&sl[0][0][0]);

    for (int i = tid; i < N_COLS; i += 256) shist[i] = 0u;

    const int c0 = tid, c1 = tid + 256, c2 = tid + 512;
    float accp0 = 0.0f, accp1 = 0.0f, accp2 = 0.0f;

    const int row0 = blockIdx.x * RPB;

#define CP_TILE(rbase, buf) do {                                                 \
        const float* _src = g_logits + (size_t)(rbase) * N_COLS;                 \
        uint32_t _d = slb + (uint32_t)(buf) * (BATCH * N_COLS * 4) + tid * 16;   \
        _Pragma("unroll")                                                        \
        for (int _i = 0; _i < 5; _i++)                                           \
            cp16(_d + _i * 4096, _src + tid * 4 + _i * 1024);                    \
        cp_commit();                                                             \
    } while (0)

    CP_TILE(row0, 0);

    for (int rbi = 0; rbi < RPB / BATCH; rbi++) {
        const int rbase = row0 + rbi * BATCH;
        const int cur   = rbi & 1;

        asm volatile("cp.async.wait_group 0;" ::: "memory");
        __syncthreads();
        if (rbi + 1 < RPB / BATCH) CP_TILE(rbase + BATCH, cur ^ 1);

        {
            const int r = warp;                 // 8 warps -> 8 rows
            const int row = rbase + r;
#pragma unroll
            for (int g = 0; g < GROUPS; g++) {
                float* lp = &sl[cur][r][g * NUM_VARS];
                // load per-lane values once into registers
                float v[NJ];
                float lv = NEG_HUGE;
#pragma unroll
                for (int j = 0; j < NJ; j++) {
                    v[j] = lp[lane + 32 * j];
                    lv = fmaxf(lv, v[j]);
                }
                const float bv = warp_max_f32(lv);
                // candidate set within THR of max
                const float cutoff = bv - GAP_THR;
                unsigned m[NJ];
                int cnt = 0, first = -1;
#pragma unroll
                for (int j = 0; j < NJ; j++) {
                    m[j] = __ballot_sync(0xffffffffu, v[j] >= cutoff);
                    cnt += __popc(m[j]);
                    if (first < 0 && m[j]) first = (__ffs(m[j]) - 1) + 32 * j;
                }
                int bi = first;
                if (cnt > 1) {   // exact fp32 recheck of every candidate
                    const float* xr = x + (size_t)row * K_DIM;
                    float bestd = NEG_HUGE; int besti = NUM_VARS;
#pragma unroll
                    for (int j = 0; j < NJ; j++) {
                        unsigned mask = m[j];
                        while (mask) {
                            int srcl = __ffs(mask) - 1;
                            mask &= mask - 1;
                            int ci = srcl + 32 * j;
                            const float* wv = g_wt + (size_t)(g * NUM_VARS + ci) * K_DIM;
                            float d = 0.0f;
#pragma unroll
                            for (int k = lane; k < K_DIM; k += 32)
                                d = fmaf(xr[k], wv[k], d);
#pragma unroll
                            for (int s = 16; s > 0; s >>= 1)
                                d += __shfl_xor_sync(0xffffffffu, d, s);
                            d += bias[g * NUM_VARS + ci];
                            if (d > bestd || (d == bestd && ci < besti)) {
                                bestd = d; besti = ci;
                            }
                        }
                    }
                    bi = besti;
                }
                // single exp pass from registers; write exp back + sumexp
                float se = 0.0f;
#pragma unroll
                for (int j = 0; j < NJ; j++) {
                    float e = __expf(v[j] - bv);
                    lp[lane + 32 * j] = e;
                    se += e;
                }
#pragma unroll
                for (int s = 16; s > 0; s >>= 1)
                    se += __shfl_xor_sync(0xffffffffu, se, s);
                if (lane == 0) {
                    sinv[r][g] = 1.0f / se;
                    sk[r][g]   = bi;
                    atomicAdd(&shist[g * NUM_VARS + bi], 1u);
                }
            }
        }
        __syncthreads();

        // softmax-prob accumulation by column owner (exp already cached)
#pragma unroll
        for (int r = 0; r < BATCH; r++) {
            float i0 = sinv[r][0], i1 = sinv[r][1];
            accp0 += sl[cur][r][c0] * i0;                        // c0 < 256 < 320
            accp1 += sl[cur][r][c1] * ((c1 < NUM_VARS) ? i0 : i1);
            if (c2 < N_COLS) accp2 += sl[cur][r][c2] * i1;       // c2 >= 512
        }

        // gather epilogue: float4, 4 rows per pass (64 lanes per row)
        {
            const int gr = tid >> 6;          // row-in-quad 0..3
            const int gc = (tid & 63) * 4;    // col 0,4,...,252
            const int gg = gc >> 7;           // group
#pragma unroll
            for (int rq = 0; rq < 2; rq++) {
                const int rr  = rq * 4 + gr;
                const int row = rbase + rr;
                const int k   = sk[rr][gg];
                float4 vv = *(const float4*)&codebook[
                    (size_t)(gg * NUM_VARS + k) * CB_DIM + (gc & 127)];
                *(float4*)&out[(size_t)row * 256 + gc] = vv;
            }
        }
    }

    __syncthreads();
    atomicAdd(&g_probsum[c0], accp0);
    atomicAdd(&g_probsum[c1], accp1);
    if (c2 < N_COLS) atomicAdd(&g_probsum[c2], accp2);
    for (int i = tid; i < N_COLS; i += 256)
        if (shist[i]) atomicAdd(&g_counts[i], shist[i]);

    // ---- last-block finalize (perplexities) ----
    __threadfence();
    __syncthreads();
    if (tid == 0) sticket = atomicAdd(&g_done, 1u);
    __syncthreads();
    if (sticket != gridDim.x - 1) return;
    __threadfence();   // acquire: see all blocks' accumulator writes

    __shared__ float redv[4][8];
    const float invN = 1.0f / (float)M_ROWS;
    float h0 = 0.0f, h1 = 0.0f, s0 = 0.0f, s1 = 0.0f;
    for (int i = tid; i < N_COLS; i += 256) {
        float ph = (float)g_counts[i] * invN;
        float ps = g_probsum[i] * invN;
        float th = ph * logf(ph + EPSV);
        float ts = ps * logf(ps + EPSV);
        if (i < NUM_VARS) { h0 += th; s0 += ts; }
        else              { h1 += th; s1 += ts; }
    }
#pragma unroll
    for (int s = 16; s > 0; s >>= 1) {
        h0 += __shfl_xor_sync(0xffffffffu, h0, s);
        h1 += __shfl_xor_sync(0xffffffffu, h1, s);
        s0 += __shfl_xor_sync(0xffffffffu, s0, s);
        s1 += __shfl_xor_sync(0xffffffffu, s1, s);
    }
    if (lane == 0) { redv[0][warp] = h0; redv[1][warp] = h1;
                     redv[2][warp] = s0; redv[3][warp] = s1; }
    __syncthreads();
    if (tid == 0) {
        float th0 = 0, th1 = 0, ts0 = 0, ts1 = 0;
#pragma unroll
        for (int w = 0; w < 8; w++) {
            th0 += redv[0][w]; th1 += redv[1][w];
            ts0 += redv[2][w]; ts1 += redv[3][w];
        }
        out2[0] = expf(-th0) + expf(-th1);   // code_perplexity
        out2[1] = expf(-ts0) + expf(-ts1);   // prob_perplexity
        g_done = 0;                          // reset ticket for graph replay
    }
}

// ---------------------------------------------------------------------------
extern "C" void kernel_launch(void* const* d_in, const int* in_sizes, int n_in,
                              void* d_out, int out_size)
{
    const float* x   = (const float*)d_in[0];   // [16,4096,512]
    const float* W   = (const float*)d_in[1];   // [512,640]
    const float* b   = (const float*)d_in[2];   // [640]
    const float* cb  = (const float*)d_in[3];   // [640,128]
    float*       out = (float*)d_out;

    cudaFuncSetAttribute(gemm_fp16_kernel,
                         cudaFuncAttributeMaxDynamicSharedMemorySize, GEMM_SMEM);

    prep_kernel<<<WPREP_BLOCKS + XPACK_BLOCKS, 256>>>(W, x);

    dim3 gg(N_COLS / 128, M_ROWS / 128);        // (5, 512)
    gemm_fp16_kernel<<<gg, 256, GEMM_SMEM>>>(b);

    reduce_kernel<<<M_ROWS / RPB, 256>>>(cb, x, b, out, out + out_size - 2);
}

// round 11
// speedup vs baseline: 1.0634x; 1.0634x over previous
#include <cuda_runtime.h>
#include <cstdint>

#define M_ROWS 65536
#define N_COLS 640
#define K_DIM  512
#define GROUPS 2
#define NUM_VARS 320
#define CB_DIM 128
#define EPSV 1e-7f
#define NEG_HUGE -3.402823466e38f
#define GAP_THR 0.25f

// ---------------------------------------------------------------------------
// Static device scratch (no cudaMalloc allowed)
// ---------------------------------------------------------------------------
__device__ float        g_logits[(size_t)M_ROWS * N_COLS];
__device__ uint32_t     g_xh[(size_t)M_ROWS * (K_DIM / 2)];     // x fp16x2, k-pair packed
__device__ float        g_wt[(size_t)N_COLS * K_DIM];           // W^T fp32 (exact recheck)
__device__ uint32_t     g_wth[(size_t)N_COLS * (K_DIM / 2)];    // W^T fp16x2, k-pair packed
__device__ float        g_probsum[N_COLS];
__device__ unsigned int g_counts[N_COLS];
__device__ unsigned int g_done;                                 // last-block ticket

// ---------------------------------------------------------------------------
// Helpers (baseline sm_103 PTX only: cp.async, mma.sync fp16, redux.sync)
// ---------------------------------------------------------------------------
__device__ __forceinline__ uint32_t smem_to_u32(const void* p) {
    uint32_t a;
    asm("{ .reg .u64 t; cvta.to.shared.u64 t, %1; cvt.u32.u64 %0, t; }" : "=r"(a) : "l"(p));
    return a;
}
__device__ __forceinline__ void cp16(uint32_t s, const void* g) {
    asm volatile("cp.async.cg.shared.global [%0], [%1], 16;" :: "r"(s), "l"(g) : "memory");
}
__device__ __forceinline__ void cp_commit() {
    asm volatile("cp.async.commit_group;" ::: "memory");
}
// pack two consecutive-k floats into fp16x2 (low half = even k)
__device__ __forceinline__ uint32_t h2pack(float e, float o) {
    uint32_t h;
    asm("cvt.rn.f16x2.f32 %0, %1, %2;" : "=r"(h) : "f"(o), "f"(e));
    return h;
}
__device__ __forceinline__ void mma_fp16(float* c, const uint32_t* a, const uint32_t* b) {
    asm volatile(
        "mma.sync.aligned.m16n8k16.row.col.f32.f16.f16.f32 "
        "{%0,%1,%2,%3}, {%4,%5,%6,%7}, {%8,%9}, {%0,%1,%2,%3};"
        : "+f"(c[0]), "+f"(c[1]), "+f"(c[2]), "+f"(c[3])
        : "r"(a[0]), "r"(a[1]), "r"(a[2]), "r"(a[3]), "r"(b[0]), "r"(b[1]));
}
// exact warp-max of a float via order-preserving u32 keys + redux.sync
__device__ __forceinline__ float warp_max_f32(float v) {
    uint32_t u = __float_as_uint(v);
    uint32_t key = ((int)u < 0) ? ~u : (u | 0x80000000u);
    uint32_t kmax;
    asm("redux.sync.max.u32 %0, %1, 0xffffffff;" : "=r"(kmax) : "r"(key));
    uint32_t ub = (kmax & 0x80000000u) ? (kmax & 0x7fffffffu) : ~kmax;
    return __uint_as_float(ub);
}

// ---------------------------------------------------------------------------
// Kernel 0: combined prep.  Blocks [0,80): W transpose (fp32 recheck copy) +
// fp16 pack.  Blocks [80,...): stream-pack x to fp16x2 (4 float4/thread).
// Block 0 also zeroes the cross-block accumulators (graph replay reset).
// ---------------------------------------------------------------------------
#define WPREP_BLOCKS 80                                      // 8 * 10
#define XPACK_TOT    (M_ROWS * (K_DIM / 4))                  // total float4s
#define XPACK_BLOCKS (XPACK_TOT / (256 * 4))                 // 8192

__global__ __launch_bounds__(256)
void prep_kernel(const float* __restrict__ W, const float* __restrict__ x) {
    const int tid = threadIdx.x;
    if (blockIdx.x >= WPREP_BLOCKS) {
        const size_t base = (size_t)(blockIdx.x - WPREP_BLOCKS) * 256 + tid;
#pragma unroll
        for (int q = 0; q < 4; q++) {
            const size_t i = base + (size_t)q * (XPACK_TOT / 4);
            const float4 v = ((const float4*)x)[i];
            uint2 o;
            o.x = h2pack(v.x, v.y);
            o.y = h2pack(v.z, v.w);
            ((uint2*)g_xh)[i] = o;
        }
        return;
    }

    __shared__ float t[64][65];
    const int kt = (blockIdx.x & 7) * 64, nt = (blockIdx.x >> 3) * 64;

    if (blockIdx.x == 0) {
        for (int i = tid; i < N_COLS; i += 256) { g_probsum[i] = 0.0f; g_counts[i] = 0u; }
    }

    for (int i = tid; i < 64 * 64; i += 256) {
        int k = i >> 6, n = i & 63;
        t[k][n] = W[(size_t)(kt + k) * N_COLS + nt + n];
    }
    __syncthreads();
    for (int i = tid; i < 64 * 64; i += 256) {
        int n = i >> 6, k = i & 63;
        g_wt[(size_t)(nt + n) * K_DIM + kt + k] = t[k][n];
    }
    for (int i = tid; i < 64 * 32; i += 256) {
        int n = i >> 5, w = i & 31;
        g_wth[(size_t)(nt + n) * (K_DIM / 2) + (kt >> 1) + w] =
            h2pack(t[2 * w][n], t[2 * w + 1][n]);
    }
}

// ---------------------------------------------------------------------------
// Kernel 1: single-pass fp16 GEMM, mma.sync.m16n8k16 (fp32 accumulate).
// R9-proven config: CTA 128x128, 8 warps (warp tile 32x64), K-chunks of 32
// fp32 (=16 words), 4-stage cp.async pipeline (80 KB smem, 2 CTAs/SM),
// one barrier per chunk.  Smem rows padded to 20 words -> conflict-free LDS.
// ---------------------------------------------------------------------------
#define SM_STRIDE 20
#define TILE_B    (128 * SM_STRIDE * 4)   // 10240 bytes per tile
#define STAGE_B   (2 * TILE_B)            // 20480 (A + B)
#define GEMM_SMEM (4 * STAGE_B)           // 81920
#define NCHUNK 16

__global__ __launch_bounds__(256, 2)
void gemm_fp16_kernel(const float* __restrict__ bias)  // b [640]
{
    extern __shared__ char smem[];
    const int tid  = threadIdx.x;
    const int wid  = tid >> 5;
    const int lane = tid & 31;
    const int bm   = blockIdx.y * 128;
    const int bn   = blockIdx.x * 128;
    const int wm   = wid & 3;      // M-warp 0..3 -> rows wm*32..+32
    const int wn   = wid >> 2;     // N-warp 0..1 -> cols wn*64..+64
    const int grp  = lane >> 2;    // 0..7
    const int tg   = lane & 3;     // 0..3
    const uint32_t sb = smem_to_u32(smem);

    float acc[2][8][4];
#pragma unroll
    for (int mf = 0; mf < 2; mf++)
#pragma unroll
        for (int nf = 0; nf < 8; nf++)
#pragma unroll
            for (int r = 0; r < 4; r++) acc[mf][nf][r] = 0.0f;

    // loader mapping: thread -> (row 0..127, half 0/1 of the 16-word chunk row)
    const int lr = tid >> 1;
    const int lh = tid & 1;
    const uint32_t* Ag = g_xh  + (size_t)(bm + lr) * (K_DIM / 2) + lh * 8;
    const uint32_t* Bg = g_wth + (size_t)(bn + lr) * (K_DIM / 2) + lh * 8;
    const uint32_t  dst = (uint32_t)(lr * SM_STRIDE + lh * 8) * 4;

#define CP_CHUNK(c, stg) do {                                                    \
        uint32_t _s = sb + (uint32_t)(stg) * STAGE_B + dst;                      \
        const uint32_t* _ga = Ag + (c) * 16;                                     \
        cp16(_s, _ga);               cp16(_s + 16, _ga + 4);                     \
        const uint32_t* _gb = Bg + (c) * 16;                                     \
        cp16(_s + TILE_B, _gb);      cp16(_s + TILE_B + 16, _gb + 4);            \
        cp_commit();                                                             \
    } while (0)

    CP_CHUNK(0, 0);
    CP_CHUNK(1, 1);
    CP_CHUNK(2, 2);

    for (int c = 0; c < NCHUNK; c++) {
        const int st = c & 3;
        if (c < NCHUNK - 2)       asm volatile("cp.async.wait_group 2;" ::: "memory");
        else if (c == NCHUNK - 2) asm volatile("cp.async.wait_group 1;" ::: "memory");
        else                      asm volatile("cp.async.wait_group 0;" ::: "memory");
        __syncthreads();

        if (c + 3 < NCHUNK) CP_CHUNK(c + 3, (c + 3) & 3);

        const uint32_t* Ah = (const uint32_t*)(smem + (size_t)st * STAGE_B);
        const uint32_t* Bh = (const uint32_t*)(smem + (size_t)st * STAGE_B + TILE_B);

#pragma unroll
        for (int ks = 0; ks < 2; ks++) {
            const int w0 = ks * 8 + tg;
            uint32_t af[2][4];
#pragma unroll
            for (int mf = 0; mf < 2; mf++) {
                const int r = wm * 32 + mf * 16 + grp;
                af[mf][0] = Ah[r * SM_STRIDE + w0];
                af[mf][1] = Ah[(r + 8) * SM_STRIDE + w0];
                af[mf][2] = Ah[r * SM_STRIDE + w0 + 4];
                af[mf][3] = Ah[(r + 8) * SM_STRIDE + w0 + 4];
            }
#pragma unroll
            for (int nf = 0; nf < 8; nf++) {
                const int nr = wn * 64 + nf * 8 + grp;
                uint32_t bf[2];
                bf[0] = Bh[nr * SM_STRIDE + w0];
                bf[1] = Bh[nr * SM_STRIDE + w0 + 4];
#pragma unroll
                for (int mf = 0; mf < 2; mf++)
                    mma_fp16(acc[mf][nf], af[mf], bf);
            }
        }
    }

    // epilogue: bias add, store logits
#pragma unroll
    for (int mf = 0; mf < 2; mf++) {
        const int row = bm + wm * 32 + mf * 16 + grp;
#pragma unroll
        for (int nf = 0; nf < 8; nf++) {
            const int col = bn + wn * 64 + nf * 8 + tg * 2;
            const float b0 = __ldg(&bias[col]);
            const float b1 = __ldg(&bias[col + 1]);
            float2 v0 = make_float2(acc[mf][nf][0] + b0, acc[mf][nf][1] + b1);
            float2 v1 = make_float2(acc[mf][nf][2] + b0, acc[mf][nf][3] + b1);
            *(float2*)&g_logits[(size_t)row * N_COLS + col]       = v0;
            *(float2*)&g_logits[(size_t)(row + 8) * N_COLS + col] = v1;
        }
    }
}

// ---------------------------------------------------------------------------
// Kernel 2: per-row argmax + softmax + codebook gather + (last block) final
// perplexities.
//  - logits tiles double-buffered via cp.async
//  - warp max via redux.sync; candidate-set exact fp32 recheck
//  - per-lane logits cached in registers (1 smem read instead of 3)
//  - gather via float4 (4 rows x 64 lanes)
//  - finalize folded in via last-block ticket
// ---------------------------------------------------------------------------
#define RPB   32
#define BATCH 8
#define NJ    (NUM_VARS / 32)    // 10

__global__ __launch_bounds__(256)
void reduce_kernel(const float* __restrict__ codebook,   // [640, 128]
                   const float* __restrict__ x,          // [65536, 512]
                   const float* __restrict__ bias,       // [640]
                   float* __restrict__ out,              // [65536, 256]
                   float* __restrict__ out2)             // 2 perplexity scalars
{
    __shared__ __align__(16) float sl[2][BATCH][N_COLS];   // 40960 B
    __shared__ float sinv[BATCH][2];
    __shared__ int   sk[BATCH][2];
    __shared__ unsigned int shist[N_COLS];
    __shared__ unsigned int sticket;

    const int tid  = threadIdx.x;
    const int lane = tid & 31;
    const int warp = tid >> 5;
    const uint32_t slb = smem_to_u32(&sl[0][0][0]);

    for (int i = tid; i < N_COLS; i += 256) shist[i] = 0u;

    const int c0 = tid, c1 = tid + 256, c2 = tid + 512;
    float accp0 = 0.0f, accp1 = 0.0f, accp2 = 0.0f;

    const int row0 = blockIdx.x * RPB;

#define CP_TILE(rbase, buf) do {                                                 \
        const float* _src = g_logits + (size_t)(rbase) * N_COLS;                 \
        uint32_t _d = slb + (uint32_t)(buf) * (BATCH * N_COLS * 4) + tid * 16;   \
        _Pragma("unroll")                                                        \
        for (int _i = 0; _i < 5; _i++)                                           \
            cp16(_d + _i * 4096, _src + tid * 4 + _i * 1024);                    \
        cp_commit();                                                             \
    } while (0)

    CP_TILE(row0, 0);

    for (int rbi = 0; rbi < RPB / BATCH; rbi++) {
        const int rbase = row0 + rbi * BATCH;
        const int cur   = rbi & 1;

        asm volatile("cp.async.wait_group 0;" ::: "memory");
        __syncthreads();
        if (rbi + 1 < RPB / BATCH) CP_TILE(rbase + BATCH, cur ^ 1);

        {
            const int r = warp;                 // 8 warps -> 8 rows
            const int row = rbase + r;
#pragma unroll
            for (int g = 0; g < GROUPS; g++) {
                float* lp = &sl[cur][r][g * NUM_VARS];
                // load per-lane values once into registers
                float v[NJ];
                float lv = NEG_HUGE;
#pragma unroll
                for (int j = 0; j < NJ; j++) {
                    v[j] = lp[lane + 32 * j];
                    lv = fmaxf(lv, v[j]);
                }
                const float bv = warp_max_f32(lv);
                // candidate set within THR of max
                const float cutoff = bv - GAP_THR;
                unsigned m[NJ];
                int cnt = 0, first = -1;
#pragma unroll
                for (int j = 0; j < NJ; j++) {
                    m[j] = __ballot_sync(0xffffffffu, v[j] >= cutoff);
                    cnt += __popc(m[j]);
                    if (first < 0 && m[j]) first = (__ffs(m[j]) - 1) + 32 * j;
                }
                int bi = first;
                if (cnt > 1) {   // exact fp32 recheck of every candidate
                    const float* xr = x + (size_t)row * K_DIM;
                    float bestd = NEG_HUGE; int besti = NUM_VARS;
#pragma unroll
                    for (int j = 0; j < NJ; j++) {
                        unsigned mask = m[j];
                        while (mask) {
                            int srcl = __ffs(mask) - 1;
                            mask &= mask - 1;
                            int ci = srcl + 32 * j;
                            const float* wv = g_wt + (size_t)(g * NUM_VARS + ci) * K_DIM;
                            float d = 0.0f;
#pragma unroll
                            for (int k = lane; k < K_DIM; k += 32)
                                d = fmaf(xr[k], wv[k], d);
#pragma unroll
                            for (int s = 16; s > 0; s >>= 1)
                                d += __shfl_xor_sync(0xffffffffu, d, s);
                            d += bias[g * NUM_VARS + ci];
                            if (d > bestd || (d == bestd && ci < besti)) {
                                bestd = d; besti = ci;
                            }
                        }
                    }
                    bi = besti;
                }
                // single exp pass from registers; write exp back + sumexp
                float se = 0.0f;
#pragma unroll
                for (int j = 0; j < NJ; j++) {
                    float e = __expf(v[j] - bv);
                    lp[lane + 32 * j] = e;
                    se += e;
                }
#pragma unroll
                for (int s = 16; s > 0; s >>= 1)
                    se += __shfl_xor_sync(0xffffffffu, se, s);
                if (lane == 0) {
                    sinv[r][g] = 1.0f / se;
                    sk[r][g]   = bi;
                    atomicAdd(&shist[g * NUM_VARS + bi], 1u);
                }
            }
        }
        __syncthreads();

        // softmax-prob accumulation by column owner (exp already cached)
#pragma unroll
        for (int r = 0; r < BATCH; r++) {
            float i0 = sinv[r][0], i1 = sinv[r][1];
            accp0 += sl[cur][r][c0] * i0;                        // c0 < 256 < 320
            accp1 += sl[cur][r][c1] * ((c1 < NUM_VARS) ? i0 : i1);
            if (c2 < N_COLS) accp2 += sl[cur][r][c2] * i1;       // c2 >= 512
        }

        // gather epilogue: float4, 4 rows per pass (64 lanes per row)
        {
            const int gr = tid >> 6;          // row-in-quad 0..3
            const int gc = (tid & 63) * 4;    // col 0,4,...,252
            const int gg = gc >> 7;           // group
#pragma unroll
            for (int rq = 0; rq < 2; rq++) {
                const int rr  = rq * 4 + gr;
                const int row = rbase + rr;
                const int k   = sk[rr][gg];
                float4 vv = *(const float4*)&codebook[
                    (size_t)(gg * NUM_VARS + k) * CB_DIM + (gc & 127)];
                *(float4*)&out[(size_t)row * 256 + gc] = vv;
            }
        }
    }

    __syncthreads();
    atomicAdd(&g_probsum[c0], accp0);
    atomicAdd(&g_probsum[c1], accp1);
    if (c2 < N_COLS) atomicAdd(&g_probsum[c2], accp2);
    for (int i = tid; i < N_COLS; i += 256)
        if (shist[i]) atomicAdd(&g_counts[i], shist[i]);

    // ---- last-block finalize (perplexities) ----
    __threadfence();
    __syncthreads();
    if (tid == 0) sticket = atomicAdd(&g_done, 1u);
    __syncthreads();
    if (sticket != gridDim.x - 1) return;
    __threadfence();   // acquire: see all blocks' accumulator writes

    __shared__ float redv[4][8];
    const float invN = 1.0f / (float)M_ROWS;
    float h0 = 0.0f, h1 = 0.0f, s0 = 0.0f, s1 = 0.0f;
    for (int i = tid; i < N_COLS; i += 256) {
        float ph = (float)g_counts[i] * invN;
        float ps = g_probsum[i] * invN;
        float th = ph * logf(ph + EPSV);
        float ts = ps * logf(ps + EPSV);
        if (i < NUM_VARS) { h0 += th; s0 += ts; }
        else              { h1 += th; s1 += ts; }
    }
#pragma unroll
    for (int s = 16; s > 0; s >>= 1) {
        h0 += __shfl_xor_sync(0xffffffffu, h0, s);
        h1 += __shfl_xor_sync(0xffffffffu, h1, s);
        s0 += __shfl_xor_sync(0xffffffffu, s0, s);
        s1 += __shfl_xor_sync(0xffffffffu, s1, s);
    }
    if (lane == 0) { redv[0][warp] = h0; redv[1][warp] = h1;
                     redv[2][warp] = s0; redv[3][warp] = s1; }
    __syncthreads();
    if (tid == 0) {
        float th0 = 0, th1 = 0, ts0 = 0, ts1 = 0;
#pragma unroll
        for (int w = 0; w < 8; w++) {
            th0 += redv[0][w]; th1 += redv[1][w];
            ts0 += redv[2][w]; ts1 += redv[3][w];
        }
        out2[0] = expf(-th0) + expf(-th1);   // code_perplexity
        out2[1] = expf(-ts0) + expf(-ts1);   // prob_perplexity
        g_done = 0;                          // reset ticket for graph replay
    }
}

// ---------------------------------------------------------------------------
extern "C" void kernel_launch(void* const* d_in, const int* in_sizes, int n_in,
                              void* d_out, int out_size)
{
    const float* x   = (const float*)d_in[0];   // [16,4096,512]
    const float* W   = (const float*)d_in[1];   // [512,640]
    const float* b   = (const float*)d_in[2];   // [640]
    const float* cb  = (const float*)d_in[3];   // [640,128]
    float*       out = (float*)d_out;

    cudaFuncSetAttribute(gemm_fp16_kernel,
                         cudaFuncAttributeMaxDynamicSharedMemorySize, GEMM_SMEM);

    prep_kernel<<<WPREP_BLOCKS + XPACK_BLOCKS, 256>>>(W, x);

    dim3 gg(N_COLS / 128, M_ROWS / 128);        // (5, 512)
    gemm_fp16_kernel<<<gg, 256, GEMM_SMEM>>>(b);

    reduce_kernel<<<M_ROWS / RPB, 256>>>(cb, x, b, out, out + out_size - 2);
}